// round 2
// baseline (speedup 1.0000x reference)
#include <cuda_runtime.h>

// ---------------- problem constants ----------------
#define NB    65536            // batch
#define GS    7                // graph size
#define INH   5                // input feature dim
#define GH    144              // gcn hidden
#define LINH  128              // linear hidden
#define MTOT  (NB*GS)          // 458752 rows
#define N2    (2*GH)           // 288: [h1 | h2] concatenated

// ---------------- device scratch (allocation-free rule: __device__ globals) ----
__device__ float g_adjn[(size_t)NB*GS*GS];   // norm_adj      12.8 MB
__device__ float g_adji[(size_t)NB*GS*GS];   // inv_norm_adj  12.8 MB
__device__ float g_X [(size_t)MTOT*GH];      // current x     264 MB
__device__ float g_Hb[(size_t)MTOT*N2];      // h1|h2         528 MB
__device__ float g_v [GH];                   // fused fc vector

// ---------------- packed fp32x2 FMA (Blackwell FFMA2; 2x FFMA-3reg rate) ----
__device__ __forceinline__ void ffma2(float2 &d, float2 a, float2 b) {
    asm("fma.rn.f32x2 %0, %1, %2, %0;"
        : "+l"(*reinterpret_cast<unsigned long long*>(&d))
        : "l"(*reinterpret_cast<unsigned long long*>(&a)),
          "l"(*reinterpret_cast<unsigned long long*>(&b)));
}

// ================= kernel 1: adjacency prep (once; reused by all 3 layers) ====
// norm_adj = rownorm(rownorm(adj+I)); inv_norm_adj = rownorm(rownorm(adj+I)^T)
__global__ void k_prep(const float* __restrict__ adj) {
    __shared__ float s[128*49];
    const int tid = threadIdx.x;
    const size_t base = (size_t)blockIdx.x * 128 * 49;

    for (int i = tid; i < 128*49; i += 128) s[i] = adj[base + i];
    __syncthreads();

    float a[49];
#pragma unroll
    for (int i = 0; i < 49; i++) a[i] = s[tid*49 + i];
    __syncthreads();                      // everyone copied; s reusable

    // a := adj_d = rownorm(adj + I)
#pragma unroll
    for (int i = 0; i < 7; i++) {
        a[i*7 + i] += 1.0f;
        float rs = 0.f;
#pragma unroll
        for (int j = 0; j < 7; j++) rs += a[i*7 + j];
        const float inv = 1.0f / rs;
#pragma unroll
        for (int j = 0; j < 7; j++) a[i*7 + j] *= inv;
    }
    // norm_adj = rownorm(adj_d)  (faithful second normalize; ~identity)
#pragma unroll
    for (int i = 0; i < 7; i++) {
        float rs = 0.f;
#pragma unroll
        for (int j = 0; j < 7; j++) rs += a[i*7 + j];
        const float inv = 1.0f / rs;
#pragma unroll
        for (int j = 0; j < 7; j++) s[tid*49 + i*7 + j] = a[i*7 + j] * inv;
    }
    __syncthreads();
    for (int i = tid; i < 128*49; i += 128) g_adjn[base + i] = s[i];
    __syncthreads();

    // inv_norm_adj[i][j] = adj_d[j][i] / colsum_i(adj_d)
#pragma unroll
    for (int i = 0; i < 7; i++) {
        float cs = 0.f;
#pragma unroll
        for (int r = 0; r < 7; r++) cs += a[r*7 + i];
        const float inv = 1.0f / cs;
#pragma unroll
        for (int j = 0; j < 7; j++) s[tid*49 + i*7 + j] = a[j*7 + i] * inv;
    }
    __syncthreads();
    for (int i = tid; i < 128*49; i += 128) g_adji[base + i] = s[i];
}

// ================= kernel 2: collapse fc2@fc1 into v[144] ======================
__global__ void k_v(const float* __restrict__ fc1, const float* __restrict__ fc2) {
    const int k = threadIdx.x;
    if (k < GH) {
        float s = 0.f;
        for (int j = 0; j < LINH; j++) s = fmaf(fc2[j], fc1[j*GH + k], s);
        g_v[k] = s;
    }
}

// ================= kernel 3: layer 0 fused (K=5 GEMM + mix + relu + avg) ======
__global__ void k_layer0(const float* __restrict__ ops,
                         const float* __restrict__ w1,
                         const float* __restrict__ w2) {
    __shared__ float sx[GS*INH];    // 35
    __shared__ float sn[49], si[49];
    const int b = blockIdx.x, tid = threadIdx.x;   // blockDim == 144

    // cooperative loads: 35 + 49 + 49 = 133 <= 144 threads (R1 bug: old scheme
    // needed tid up to 145 for si and left si[47..48] uninitialized)
    if (tid < 35)                      sx[tid]      = ops[(size_t)b*35 + tid];
    else if (tid < 84)                 sn[tid-35]   = g_adjn[(size_t)b*49 + (tid-35)];
    else if (tid < 133)                si[tid-84]   = g_adji[(size_t)b*49 + (tid-84)];
    __syncthreads();

    const int k = tid;
    float w1v[INH], w2v[INH];
#pragma unroll
    for (int t = 0; t < INH; t++) { w1v[t] = w1[t*GH + k]; w2v[t] = w2[t*GH + k]; }

    float h1[GS], h2[GS];
#pragma unroll
    for (int j = 0; j < GS; j++) {
        float a1 = 0.f, a2 = 0.f;
#pragma unroll
        for (int t = 0; t < INH; t++) {
            const float xv = sx[j*INH + t];
            a1 = fmaf(xv, w1v[t], a1);
            a2 = fmaf(xv, w2v[t], a2);
        }
        h1[j] = a1; h2[j] = a2;
    }
#pragma unroll
    for (int i = 0; i < GS; i++) {
        float o1 = 0.f, o2 = 0.f;
#pragma unroll
        for (int j = 0; j < GS; j++) {
            o1 = fmaf(sn[i*7 + j], h1[j], o1);
            o2 = fmaf(si[i*7 + j], h2[j], o2);
        }
        o1 = fmaxf(o1, 0.f); o2 = fmaxf(o2, 0.f);
        g_X[(size_t)(b*GS + i)*GH + k] = 0.5f * (o1 + o2);
    }
}

// ================= kernel 4: big GEMM  H[:,y*144:(y+1)*144] = X @ W(y) ========
// M=458752, N=144 per y, K=144.  MT=64 rows/CTA, 256 thr, thread tile 4r x 9c.
#define MT 64
#define KS 16
__global__ __launch_bounds__(256) void k_gemm(const float* __restrict__ w1,
                                              const float* __restrict__ w2) {
    const float* __restrict__ Wg = blockIdx.y ? w2 : w1;
    __shared__ float Xt[KS][MT];     // transposed X tile
    __shared__ float Wt[KS][GH];     // 16 x 144

    const int tid = threadIdx.x;
    const int tn = tid & 15, tm = tid >> 4;
    const int row0 = blockIdx.x * MT;

    float2 acc2[4][4];
    float  acc1[4];
#pragma unroll
    for (int r = 0; r < 4; r++) {
        acc1[r] = 0.f;
#pragma unroll
        for (int p = 0; p < 4; p++) acc2[r][p] = make_float2(0.f, 0.f);
    }

    const int lrow = tid >> 2;            // 0..63
    const int lk4  = (tid & 3) * 4;       // 0,4,8,12
    const float* Xg = g_X + (size_t)(row0 + lrow)*GH + lk4;

    for (int k0 = 0; k0 < GH; k0 += KS) {
        const float4 xv = *reinterpret_cast<const float4*>(Xg + k0);
        Xt[lk4+0][lrow] = xv.x; Xt[lk4+1][lrow] = xv.y;
        Xt[lk4+2][lrow] = xv.z; Xt[lk4+3][lrow] = xv.w;
#pragma unroll
        for (int r = 0; r < 9; r++) {
            const unsigned lin = r*256u + (unsigned)tid;     // < 2304
            const unsigned kk = lin / GH, cc = lin - kk*GH;
            Wt[kk][cc] = Wg[(size_t)(k0 + kk)*GH + cc];
        }
        __syncthreads();
#pragma unroll
        for (int kk = 0; kk < KS; kk++) {
            const float4 av = *reinterpret_cast<const float4*>(&Xt[kk][tm*4]);
            float wv[9];
#pragma unroll
            for (int c = 0; c < 9; c++) wv[c] = Wt[kk][tn + 16*c];
            const float ar[4] = {av.x, av.y, av.z, av.w};
#pragma unroll
            for (int r = 0; r < 4; r++) {
                const float2 a2 = make_float2(ar[r], ar[r]);
#pragma unroll
                for (int p = 0; p < 4; p++) {
                    const float2 b2 = make_float2(wv[2*p], wv[2*p+1]);
                    ffma2(acc2[r][p], a2, b2);
                }
                acc1[r] = fmaf(ar[r], wv[8], acc1[r]);
            }
        }
        __syncthreads();
    }

    const int ncol0 = blockIdx.y * GH;
#pragma unroll
    for (int r = 0; r < 4; r++) {
        float* out = g_Hb + (size_t)(row0 + tm*4 + r)*N2 + ncol0 + tn;
#pragma unroll
        for (int p = 0; p < 4; p++) {
            out[16*(2*p)  ] = acc2[r][p].x;
            out[16*(2*p+1)] = acc2[r][p].y;
        }
        out[16*8] = acc1[r];
    }
}

// ================= kernel 5: mix (adj apply + relu + avg), optional final =====
__global__ void k_mix(int is_final, const float* __restrict__ nv,
                      float* __restrict__ out) {
    __shared__ float sn[49], si[49], sred[160];
    const int b = blockIdx.x, tid = threadIdx.x;   // blockDim == 144

    if (tid < 49)                    sn[tid]    = g_adjn[(size_t)b*49 + tid];
    else if (tid >= 64 && tid < 113) si[tid-64] = g_adji[(size_t)b*49 + (tid-64)];
    __syncthreads();

    const int k = tid;
    float h1[GS], h2[GS];
    const float* hb = g_Hb + (size_t)b*GS*N2 + k;
#pragma unroll
    for (int j = 0; j < GS; j++) { h1[j] = hb[j*N2]; h2[j] = hb[j*N2 + GH]; }

    float colsum = 0.f;
#pragma unroll
    for (int i = 0; i < GS; i++) {
        float o1 = 0.f, o2 = 0.f;
#pragma unroll
        for (int j = 0; j < GS; j++) {
            o1 = fmaf(sn[i*7 + j], h1[j], o1);
            o2 = fmaf(si[i*7 + j], h2[j], o2);
        }
        const float x = 0.5f * (fmaxf(o1, 0.f) + fmaxf(o2, 0.f));
        if (!is_final) g_X[(size_t)(b*GS + i)*GH + k] = x;
        else           colsum += x;
    }

    if (is_final) {
        sred[tid] = colsum * g_v[k];
        __syncthreads();
        if (tid < 16) sred[tid] += sred[tid + 128];
        __syncthreads();
        for (int s = 64; s >= 1; s >>= 1) {
            if (tid < s) sred[tid] += sred[tid + s];
            __syncthreads();
        }
        if (tid == 0) out[b] = sred[0] / nv[b];
    }
}

// ================= launch ======================================================
extern "C" void kernel_launch(void* const* d_in, const int* in_sizes, int n_in,
                              void* d_out, int out_size) {
    const float* ops  = (const float*)d_in[0];
    const float* adj  = (const float*)d_in[1];
    const float* nv   = (const float*)d_in[2];
    const float* w1_0 = (const float*)d_in[3];
    const float* w2_0 = (const float*)d_in[4];
    const float* w1_1 = (const float*)d_in[5];
    const float* w2_1 = (const float*)d_in[6];
    const float* w1_2 = (const float*)d_in[7];
    const float* w2_2 = (const float*)d_in[8];
    const float* fc1  = (const float*)d_in[9];
    const float* fc2  = (const float*)d_in[10];
    float* out = (float*)d_out;

    k_prep  <<<NB/128, 128>>>(adj);
    k_v     <<<1, GH>>>(fc1, fc2);
    k_layer0<<<NB, GH>>>(ops, w1_0, w2_0);

    dim3 gg(MTOT/MT, 2);
    k_gemm<<<gg, 256>>>(w1_1, w2_1);     // layer 1 GEMMs
    k_mix <<<NB, GH>>>(0, nv, out);      // layer 1 mix -> g_X
    k_gemm<<<gg, 256>>>(w1_2, w2_2);     // layer 2 GEMMs
    k_mix <<<NB, GH>>>(1, nv, out);      // layer 2 mix + pool + fused FC -> out
}

// round 5
// speedup vs baseline: 1.5199x; 1.5199x over previous
#include <cuda_runtime.h>
#include <cuda_bf16.h>
#include <cstdint>

// ---------------- problem constants ----------------
#define NB     65536
#define GS     7
#define INH    5
#define GH     144
#define LINH   128
#define MTOT   (NB*GS)        // 458752 rows
#define MT     112            // rows per CTA = 16 whole graphs
#define NCTA   (MTOT/MT)      // 4096
#define NWARP  14
#define NTHR   (NWARP*32)     // 448
#define KT     9              // 144/16 k-tiles
#define NT     18             // 144/8 n-tiles per warp
#define HS     292            // smem h row stride (pad vs 288)
#define ABLK   1024           // bytes per (mtile,ktile) frag block (32 lanes x 8 regs)
#define AMT    (KT*ABLK)      // 9216 bytes per mtile
#define BBLK   512            // bytes per (ktile,ntile) frag block (32 lanes x 4 regs)
#define BSLOT  (KT*NT*BBLK)   // 82944 bytes per weight slot

// ---------------- device scratch ----------------
__device__ float g_adjn[(size_t)NB*GS*GS];                 // 12.8 MB
__device__ float g_adji[(size_t)NB*GS*GS];                 // 12.8 MB
__device__ unsigned char g_X[(size_t)(MTOT/16)*AMT];       // 264 MB frag-packed hi|lo bf16
__device__ unsigned char g_B[4*BSLOT];                     // 4 weight slots
__device__ float g_v[GH];

// ---------------- helpers ----------------
__device__ __forceinline__ uint32_t pack_bf16(float a, float b) {
    __nv_bfloat162 t = __floats2bfloat162_rn(a, b);   // a in low half
    return *(uint32_t*)&t;
}
__device__ __forceinline__ void hilo(float x, float& hi, float& lo) {
    hi = __bfloat162float(__float2bfloat16(x));
    lo = x - hi;
}
__device__ __forceinline__ void mma_bf16(float* c, uint32_t a0, uint32_t a1,
                                         uint32_t a2, uint32_t a3,
                                         uint32_t b0, uint32_t b1) {
    asm volatile(
        "mma.sync.aligned.m16n8k16.row.col.f32.bf16.bf16.f32 "
        "{%0,%1,%2,%3}, {%4,%5,%6,%7}, {%8,%9}, {%0,%1,%2,%3};"
        : "+f"(c[0]), "+f"(c[1]), "+f"(c[2]), "+f"(c[3])
        : "r"(a0), "r"(a1), "r"(a2), "r"(a3), "r"(b0), "r"(b1));
}

// ---------------- shared memory layout ----------------
struct SMem {
    float h[MT*HS];        // 112 x 292 fp32 GEMM results [h1 | h2]
    float adjn[16*49];
    float adji[16*49];
    float rowsum[MT];
    float extra[2048];     // L0: ops(560)+w1(720)+w2(720); final: v(144)
};
#define SMEMB ((int)sizeof(SMem))

// ================= kernel 1: adjacency prep ====================================
__global__ void k_prep(const float* __restrict__ adj) {
    __shared__ float s[128*49];
    const int tid = threadIdx.x;
    const size_t base = (size_t)blockIdx.x * 128 * 49;

    for (int i = tid; i < 128*49; i += 128) s[i] = adj[base + i];
    __syncthreads();
    float a[49];
#pragma unroll
    for (int i = 0; i < 49; i++) a[i] = s[tid*49 + i];
    __syncthreads();

#pragma unroll
    for (int i = 0; i < 7; i++) {
        a[i*7 + i] += 1.0f;
        float rs = 0.f;
#pragma unroll
        for (int j = 0; j < 7; j++) rs += a[i*7 + j];
        const float inv = 1.0f / rs;
#pragma unroll
        for (int j = 0; j < 7; j++) a[i*7 + j] *= inv;
    }
#pragma unroll
    for (int i = 0; i < 7; i++) {
        float rs = 0.f;
#pragma unroll
        for (int j = 0; j < 7; j++) rs += a[i*7 + j];
        const float inv = 1.0f / rs;
#pragma unroll
        for (int j = 0; j < 7; j++) s[tid*49 + i*7 + j] = a[i*7 + j] * inv;
    }
    __syncthreads();
    for (int i = tid; i < 128*49; i += 128) g_adjn[base + i] = s[i];
    __syncthreads();
#pragma unroll
    for (int i = 0; i < 7; i++) {
        float cs = 0.f;
#pragma unroll
        for (int r = 0; r < 7; r++) cs += a[r*7 + i];
        const float inv = 1.0f / cs;
#pragma unroll
        for (int j = 0; j < 7; j++) s[tid*49 + i*7 + j] = a[j*7 + i] * inv;
    }
    __syncthreads();
    for (int i = tid; i < 128*49; i += 128) g_adji[base + i] = s[i];
}

// ================= kernel 2: v = fc1^T fc2 ====================================
__global__ void k_v(const float* __restrict__ fc1, const float* __restrict__ fc2) {
    const int k = threadIdx.x;
    if (k < GH) {
        float s = 0.f;
        for (int j = 0; j < LINH; j++) s = fmaf(fc2[j], fc1[j*GH + k], s);
        g_v[k] = s;
    }
}

// ================= kernel 3: pack weights into B fragments ====================
// slot order: 0=w1_1 1=w2_1 2=w1_2 3=w2_2.  B[k][n] = W[k*144+n] (col-major frag)
__global__ void k_bprep(const float* __restrict__ a, const float* __restrict__ b,
                        const float* __restrict__ c, const float* __restrict__ d) {
    const float* W = blockIdx.x == 0 ? a : blockIdx.x == 1 ? b
                   : blockIdx.x == 2 ? c : d;
    unsigned char* out = g_B + (size_t)blockIdx.x * BSLOT;
    for (int f = threadIdx.x; f < KT*NT*32; f += 256) {
        const int kt = f / (NT*32);
        const int nt = (f / 32) % NT;
        const int l  = f & 31;
        const int n  = nt*8 + (l >> 2);
        const int kb = kt*16 + (l & 3)*2;
        float w0 = W[(kb+0)*GH + n], w1 = W[(kb+1)*GH + n];
        float w8 = W[(kb+8)*GH + n], w9 = W[(kb+9)*GH + n];
        float h0,l0,h1,l1,h8,l8,h9,l9;
        hilo(w0,h0,l0); hilo(w1,h1,l1); hilo(w8,h8,l8); hilo(w9,h9,l9);
        uint4 v;
        v.x = pack_bf16(h0,h1); v.y = pack_bf16(h8,h9);
        v.z = pack_bf16(l0,l1); v.w = pack_bf16(l8,l9);
        *(uint4*)(out + (size_t)(kt*NT + nt)*BBLK + l*16) = v;
    }
}

// ================= shared mix epilogue =========================================
// Reads s->h (112 x [h1|h2]), applies adjacency mix + relu.
// !FINAL: writes next-layer X in frag-packed split-bf16 (in place, own rows only)
// FINAL:  accumulates (x . v) per row, then per-graph pooled output.
__device__ __forceinline__ float mixval(SMem* s, int row, int k) {
    const int g  = row / 7;
    const int b7 = g * 7;
    const int ii = row - b7;
    float o1 = 0.f, o2 = 0.f;
#pragma unroll
    for (int j = 0; j < 7; j++) {
        const float* hr = &s->h[(b7 + j)*HS];
        o1 = fmaf(s->adjn[g*49 + ii*7 + j], hr[k],       o1);
        o2 = fmaf(s->adji[g*49 + ii*7 + j], hr[GH + k],  o2);
    }
    return 0.5f * (fmaxf(o1, 0.f) + fmaxf(o2, 0.f));
}

template <bool FINAL>
__device__ void mix_epilogue(SMem* s, int cta, const float* __restrict__ nv,
                             float* __restrict__ out) {
    const int tid = threadIdx.x;
    if (FINAL) {
        for (int i = tid; i < MT; i += NTHR) s->rowsum[i] = 0.f;
        if (tid < GH) s->extra[tid] = g_v[tid];
    }
    __syncthreads();   // h complete + rowsum/v ready

    for (int f = tid; f < 7*KT*32; f += NTHR) {
        const int mtl = f / (KT*32);
        const int kt  = (f / 32) % KT;
        const int l   = f & 31;
        const int r0  = mtl*16 + (l >> 2);
        const int r1  = r0 + 8;
        const int kb  = kt*16 + (l & 3)*2;
        float xs[8];
        xs[0] = mixval(s, r0, kb);     xs[1] = mixval(s, r0, kb+1);
        xs[2] = mixval(s, r1, kb);     xs[3] = mixval(s, r1, kb+1);
        xs[4] = mixval(s, r0, kb+8);   xs[5] = mixval(s, r0, kb+9);
        xs[6] = mixval(s, r1, kb+8);   xs[7] = mixval(s, r1, kb+9);

        if (!FINAL) {
            float h[8], lo[8];
#pragma unroll
            for (int q = 0; q < 8; q++) hilo(xs[q], h[q], lo[q]);
            uint4 vh, vl;
            vh.x = pack_bf16(h[0], h[1]);  vh.y = pack_bf16(h[2], h[3]);
            vh.z = pack_bf16(h[4], h[5]);  vh.w = pack_bf16(h[6], h[7]);
            vl.x = pack_bf16(lo[0], lo[1]); vl.y = pack_bf16(lo[2], lo[3]);
            vl.z = pack_bf16(lo[4], lo[5]); vl.w = pack_bf16(lo[6], lo[7]);
            uint4* p = (uint4*)(g_X + ((size_t)(cta*7 + mtl)*KT + kt)*ABLK);
            p[l*2]     = vh;
            p[l*2 + 1] = vl;
        } else {
            const float* v = s->extra;
            float p0 = xs[0]*v[kb] + xs[1]*v[kb+1] + xs[4]*v[kb+8] + xs[5]*v[kb+9];
            float p1 = xs[2]*v[kb] + xs[3]*v[kb+1] + xs[6]*v[kb+8] + xs[7]*v[kb+9];
            atomicAdd(&s->rowsum[r0], p0);
            atomicAdd(&s->rowsum[r1], p1);
        }
    }

    if (FINAL) {
        __syncthreads();
        if (tid < 16) {
            float a = 0.f;
#pragma unroll
            for (int j = 0; j < 7; j++) a += s->rowsum[tid*7 + j];
            const int b = cta*16 + tid;
            out[b] = a / nv[b];
        }
    }
}

__device__ __forceinline__ void load_adj(SMem* s, int cta) {
    for (int i = threadIdx.x; i < 16*49; i += NTHR) {
        s->adjn[i] = g_adjn[(size_t)cta*784 + i];
        s->adji[i] = g_adji[(size_t)cta*784 + i];
    }
}

// ================= kernel 4: layer 0 (fp32 K=5 GEMM) + mix -> frag X ==========
__global__ void __launch_bounds__(NTHR, 1)
k_L0(const float* __restrict__ ops, const float* __restrict__ w1,
     const float* __restrict__ w2) {
    extern __shared__ unsigned char smraw[];
    SMem* s = (SMem*)smraw;
    const int cta = blockIdx.x, tid = threadIdx.x;

    load_adj(s, cta);
    for (int q = tid; q < 560; q += NTHR) s->extra[q] = ops[(size_t)cta*560 + q];
    for (int q = tid; q < 720; q += NTHR) {
        s->extra[560  + q] = w1[q];
        s->extra[1280 + q] = w2[q];
    }
    __syncthreads();

    for (int idx = tid; idx < MT*288; idx += NTHR) {
        const int i = idx / 288, c = idx % 288;
        const int k = (c < GH) ? c : c - GH;
        const float* W  = &s->extra[560 + (c < GH ? 0 : 720) + k];
        const float* xi = &s->extra[i*5];
        float h = 0.f;
#pragma unroll
        for (int t = 0; t < INH; t++) h = fmaf(xi[t], W[t*GH], h);
        s->h[i*HS + c] = h;
    }
    mix_epilogue<false>(s, cta, nullptr, nullptr);
}

// ================= kernel 5: fused HMMA GEMM + mix =============================
// grid.x = 4096 CTAs x 14 warps: warp = (wr 0..6 rows) x (wc 0..1 weight)
__global__ void __launch_bounds__(NTHR, 1)
k_gemmix(int slot0, int is_final, const float* __restrict__ nv,
         float* __restrict__ out) {
    extern __shared__ unsigned char smraw[];
    SMem* s = (SMem*)smraw;
    const int cta = blockIdx.x, tid = threadIdx.x;
    const int wid = tid >> 5, lane = tid & 31;
    const int wr = wid % 7, wc = wid / 7;

    load_adj(s, cta);

    const uint4* __restrict__ Ab =
        (const uint4*)(g_X + (size_t)(cta*7 + wr) * AMT);
    const uint4* __restrict__ Bb =
        (const uint4*)(g_B + (size_t)(slot0 + wc) * BSLOT);

    float acc[NT][4];
#pragma unroll
    for (int t = 0; t < NT; t++)
#pragma unroll
        for (int q = 0; q < 4; q++) acc[t][q] = 0.f;

#pragma unroll
    for (int kt = 0; kt < KT; kt++) {
        const uint4 ah = Ab[kt*64 + lane*2];
        const uint4 al = Ab[kt*64 + lane*2 + 1];
#pragma unroll
        for (int nt = 0; nt < NT; nt++) {
            const uint4 b = Bb[(kt*NT + nt)*32 + lane];
            mma_bf16(acc[nt], ah.x, ah.y, ah.z, ah.w, b.x, b.y);  // hi*hi
            mma_bf16(acc[nt], ah.x, ah.y, ah.z, ah.w, b.z, b.w);  // hi*lo
            mma_bf16(acc[nt], al.x, al.y, al.z, al.w, b.x, b.y);  // lo*hi
        }
    }

    // stage results to smem: rows wr*16 + l/4 (+8), cols wc*144 + nt*8 + (l%4)*2
    const int row0 = wr*16 + (lane >> 2);
    const int colb = wc*GH + (lane & 3)*2;
#pragma unroll
    for (int nt = 0; nt < NT; nt++) {
        const int col = colb + nt*8;
        s->h[row0*HS + col]       = acc[nt][0];
        s->h[row0*HS + col + 1]   = acc[nt][1];
        s->h[(row0+8)*HS + col]   = acc[nt][2];
        s->h[(row0+8)*HS + col+1] = acc[nt][3];
    }

    if (is_final) mix_epilogue<true>(s, cta, nv, out);
    else          mix_epilogue<false>(s, cta, nullptr, nullptr);
}

// ================= launch ======================================================
extern "C" void kernel_launch(void* const* d_in, const int* in_sizes, int n_in,
                              void* d_out, int out_size) {
    const float* ops  = (const float*)d_in[0];
    const float* adj  = (const float*)d_in[1];
    const float* nv   = (const float*)d_in[2];
    const float* w1_0 = (const float*)d_in[3];
    const float* w2_0 = (const float*)d_in[4];
    const float* w1_1 = (const float*)d_in[5];
    const float* w2_1 = (const float*)d_in[6];
    const float* w1_2 = (const float*)d_in[7];
    const float* w2_2 = (const float*)d_in[8];
    const float* fc1  = (const float*)d_in[9];
    const float* fc2  = (const float*)d_in[10];
    float* out = (float*)d_out;

    static int configured = 0;
    if (!configured) {
        cudaFuncSetAttribute(k_L0,     cudaFuncAttributeMaxDynamicSharedMemorySize, SMEMB);
        cudaFuncSetAttribute(k_gemmix, cudaFuncAttributeMaxDynamicSharedMemorySize, SMEMB);
        configured = 1;
    }

    k_prep <<<NB/128, 128>>>(adj);
    k_v    <<<1, GH>>>(fc1, fc2);
    k_bprep<<<4, 256>>>(w1_1, w2_1, w1_2, w2_2);
    k_L0   <<<NCTA, NTHR, SMEMB>>>(ops, w1_0, w2_0);
    k_gemmix<<<NCTA, NTHR, SMEMB>>>(0, 0, nv, out);   // layer 1
    k_gemmix<<<NCTA, NTHR, SMEMB>>>(2, 1, nv, out);   // layer 2 + pool + fc
}